// round 17
// baseline (speedup 1.0000x reference)
#include <cuda_runtime.h>
#include <cuda_fp16.h>
#include <cstdint>

// Problem constants
#define B_   8
#define S_   1024
#define D_   1024
#define H_   16
#define HD_  64
#define MROWS (B_ * S_)      // 8192

// ---------------- scratch (static device globals, fp16) ---------------------
__device__ __half g_xh[(size_t)MROWS * D_];
__device__ __half g_Wh[4][(size_t)D_ * D_];
__device__ __half g_Qh[(size_t)MROWS * D_];
__device__ __half g_Kh[(size_t)MROWS * D_];
__device__ __half g_Vh[(size_t)MROWS * D_];
__device__ __half g_Ch[(size_t)MROWS * D_];

// ============================================================================
// Helpers
// ============================================================================
__device__ __forceinline__ uint32_t smem_u32(const void* p) {
    uint32_t a;
    asm("{ .reg .u64 t; cvta.to.shared.u64 t, %1; cvt.u32.u64 %0, t; }"
        : "=r"(a) : "l"(p));
    return a;
}
__device__ __forceinline__ uint32_t f2h2(float lo, float hi) {
    uint32_t r;
    asm("cvt.rn.f16x2.f32 %0, %1, %2;" : "=r"(r) : "f"(hi), "f"(lo));
    return r;
}
__device__ __forceinline__ void ldsm_x4(uint32_t& r0, uint32_t& r1,
                                        uint32_t& r2, uint32_t& r3, uint32_t a) {
    asm volatile("ldmatrix.sync.aligned.m8n8.x4.shared.b16 {%0,%1,%2,%3}, [%4];"
                 : "=r"(r0), "=r"(r1), "=r"(r2), "=r"(r3) : "r"(a));
}
__device__ __forceinline__ void ldsm_x4_t(uint32_t& r0, uint32_t& r1,
                                          uint32_t& r2, uint32_t& r3, uint32_t a) {
    asm volatile("ldmatrix.sync.aligned.m8n8.x4.trans.shared.b16 {%0,%1,%2,%3}, [%4];"
                 : "=r"(r0), "=r"(r1), "=r"(r2), "=r"(r3) : "r"(a));
}
__device__ __forceinline__ void mma_f16(float* c, const uint32_t* a, const uint32_t* b) {
    asm volatile(
        "mma.sync.aligned.m16n8k16.row.col.f32.f16.f16.f32 "
        "{%0,%1,%2,%3}, {%4,%5,%6,%7}, {%8,%9}, {%0,%1,%2,%3};"
        : "+f"(c[0]), "+f"(c[1]), "+f"(c[2]), "+f"(c[3])
        : "r"(a[0]), "r"(a[1]), "r"(a[2]), "r"(a[3]), "r"(b[0]), "r"(b[1]));
}
#define CP16(dst, src) \
    asm volatile("cp.async.cg.shared.global [%0], [%1], 16;" \
                 :: "r"(dst), "l"(src) : "memory")
#define CP_COMMIT() asm volatile("cp.async.commit_group;" ::: "memory")
#define CP_WAIT1()  asm volatile("cp.async.wait_group 1;" ::: "memory")
#define CP_WAIT0()  asm volatile("cp.async.wait_group 0;" ::: "memory")

// fast exp on the FFMA pipe (no MUFU)
__device__ __forceinline__ float fast_exp(float x) {
    x = fminf(fmaxf(x, -80.f), 80.f);
    float y = x * 1.44269504088896341f;
    float nf = rintf(y);
    float f = y - nf;
    float p = 1.33335581e-3f;
    p = fmaf(p, f, 9.61812911e-3f);
    p = fmaf(p, f, 5.55041087e-2f);
    p = fmaf(p, f, 2.40226507e-1f);
    p = fmaf(p, f, 6.93147180e-1f);
    p = fmaf(p, f, 1.0f);
    return p * __int_as_float((127 + (int)nf) << 23);
}

// ============================================================================
// fp32 -> fp16 bulk convert (8 elems/thread)
// ============================================================================
__global__ __launch_bounds__(256)
void f32_to_f16(const float* __restrict__ s, __half* __restrict__ d, int n) {
    int i = (blockIdx.x * 256 + threadIdx.x) * 8;
    if (i < n) {
        float4 a = *(const float4*)(s + i);
        float4 b = *(const float4*)(s + i + 4);
        uint4 o = {f2h2(a.x, a.y), f2h2(a.z, a.w), f2h2(b.x, b.y), f2h2(b.z, b.w)};
        *(uint4*)(d + i) = o;
    }
}

// ============================================================================
// Projection GEMM, fp16 in, cp.async double-buffered, mma.sync m16n8k16.
// C[m,n] = sum_k A[m,k]*W[n,k] + bias[n]. CTA 128x128, BK=32, 2 CTAs/SM.
// ============================================================================
#define PRS 40                         // halfs per smem row
#define PR_STAGE (128 * PRS)           // halfs per operand stage

template <bool OUT_HALF>
__global__ __launch_bounds__(256, 2)
void proj_h(const __half* __restrict__ A, const __half* __restrict__ W,
            const float* __restrict__ bias, void* __restrict__ Cv) {
    __shared__ __half SA[2 * PR_STAGE];
    __shared__ __half SW[2 * PR_STAGE];
    const uint32_t sa = smem_u32(SA);
    const uint32_t sw = smem_u32(SW);

    const int tid = threadIdx.x;
    const int wid = tid >> 5;
    const int lane = tid & 31;
    const int wm = (wid & 3) * 32;
    const int wn = (wid >> 2) * 64;
    const int m0 = blockIdx.y * 128;
    const int n0 = blockIdx.x * 128;

    const int row  = tid >> 1;
    const int part = tid & 1;
    const __half* Ap = A + (size_t)(m0 + row) * D_ + part * 16;
    const __half* Wp = W + (size_t)(n0 + row) * D_ + part * 16;
    const uint32_t sdst = (uint32_t)(row * PRS * 2 + part * 32);

    float acc[2][8][4];
    #pragma unroll
    for (int i = 0; i < 2; i++)
        #pragma unroll
        for (int j = 0; j < 8; j++)
            #pragma unroll
            for (int q = 0; q < 4; q++) acc[i][j][q] = 0.f;

    // prefetch chunk 0 -> stage 0
    {
        CP16(sa + sdst,      Ap);
        CP16(sa + sdst + 16, Ap + 8);
        CP16(sw + sdst,      Wp);
        CP16(sw + sdst + 16, Wp + 8);
        CP_COMMIT();
    }

    for (int c = 0; c < 32; c++) {
        if (c + 1 < 32) {
            uint32_t so = (uint32_t)(((c + 1) & 1) * PR_STAGE * 2);
            const __half* ap = Ap + (c + 1) * 32;
            const __half* wp = Wp + (c + 1) * 32;
            CP16(sa + so + sdst,      ap);
            CP16(sa + so + sdst + 16, ap + 8);
            CP16(sw + so + sdst,      wp);
            CP16(sw + so + sdst + 16, wp + 8);
            CP_COMMIT();
            CP_WAIT1();
        } else {
            CP_WAIT0();
        }
        __syncthreads();
        {
            uint32_t ba = sa + (uint32_t)((c & 1) * PR_STAGE * 2);
            uint32_t bw = sw + (uint32_t)((c & 1) * PR_STAGE * 2);
            #pragma unroll
            for (int s = 0; s < 2; s++) {
                uint32_t af[2][4];
                #pragma unroll
                for (int ms = 0; ms < 2; ms++) {
                    uint32_t addr = ba + (uint32_t)((wm + ms * 16 + (lane & 15)) * PRS * 2
                                   + (s * 2 + (lane >> 4)) * 16);
                    ldsm_x4(af[ms][0], af[ms][1], af[ms][2], af[ms][3], addr);
                }
                #pragma unroll
                for (int p = 0; p < 4; p++) {
                    uint32_t bf0[2], bf1[2];
                    uint32_t addr = bw + (uint32_t)((wn + p * 16 + (lane & 7) + ((lane & 16) >> 1)) * PRS * 2
                                   + (s * 2 + ((lane >> 3) & 1)) * 16);
                    ldsm_x4(bf0[0], bf0[1], bf1[0], bf1[1], addr);
                    mma_f16(acc[0][2 * p],     af[0], bf0);
                    mma_f16(acc[1][2 * p],     af[1], bf0);
                    mma_f16(acc[0][2 * p + 1], af[0], bf1);
                    mma_f16(acc[1][2 * p + 1], af[1], bf1);
                }
            }
        }
        __syncthreads();
    }

    const int g = lane >> 2;
    const int t = lane & 3;
    #pragma unroll
    for (int j = 0; j < 8; j++) {
        int col = n0 + wn + j * 8 + 2 * t;
        float2 bv = *(const float2*)(bias + col);
        #pragma unroll
        for (int ms = 0; ms < 2; ms++) {
            int r0 = m0 + wm + ms * 16 + g;
            if (OUT_HALF) {
                __half* C = (__half*)Cv;
                *(uint32_t*)(C + (size_t)r0 * D_ + col) =
                    f2h2(acc[ms][j][0] + bv.x, acc[ms][j][1] + bv.y);
                *(uint32_t*)(C + (size_t)(r0 + 8) * D_ + col) =
                    f2h2(acc[ms][j][2] + bv.x, acc[ms][j][3] + bv.y);
            } else {
                float* C = (float*)Cv;
                *(float2*)(C + (size_t)r0 * D_ + col) =
                    make_float2(acc[ms][j][0] + bv.x, acc[ms][j][1] + bv.y);
                *(float2*)(C + (size_t)(r0 + 8) * D_ + col) =
                    make_float2(acc[ms][j][2] + bv.x, acc[ms][j][3] + bv.y);
            }
        }
    }
}

// ============================================================================
// Fused attention v3 (score-stash, half-k-tile, 2 CTAs/SM):
// Each 128-k tile processed in two 64-col halves -> C[8][4] (32 regs) ->
// fits 128-reg cap -> 2 CTAs/SM (16 warps). Pass 1 writes raw scaled scores
// + online (m,l); pass 2 reads back, normalizes in place, PV from registers.
// ============================================================================
#define ATS 72                          // halfs per smem row
#define AT_TILE (128 * ATS)             // halfs per tile
#define ATT_SMEM (3 * AT_TILE * 2)      // Q + 2 staging = 55296 bytes

__global__ __launch_bounds__(256, 2)
void attn_fused(const __half* __restrict__ Q, const __half* __restrict__ K,
                const __half* __restrict__ V, float* __restrict__ attn,
                __half* __restrict__ ctx) {
    extern __shared__ __half smh[];
    const uint32_t qsb = smem_u32(smh);
    const uint32_t stg = qsb + AT_TILE * 2;   // staging stage 0; stage 1 at +AT_TILE*2

    const int tid = threadIdx.x;
    const int wid = tid >> 5;
    const int lane = tid & 31;
    const int g = lane >> 2;
    const int t = lane & 3;
    const int wq = wid * 16;
    const int qt = blockIdx.x;
    const int bh = blockIdx.y;
    const int b  = bh >> 4;
    const int h  = bh & 15;

    const int row  = tid >> 1;
    const int part = tid & 1;
    const uint32_t kst = (uint32_t)(row * ATS * 2 + part * 64);

    // ---- load Q strip [128][64] halfs ----
    {
        const __half* qp = Q + ((size_t)(b * S_ + qt * 128 + row)) * D_ + h * HD_ + part * 32;
        *(uint4*)((char*)smh + kst)      = *(const uint4*)(qp);
        *(uint4*)((char*)smh + kst + 16) = *(const uint4*)(qp + 8);
        *(uint4*)((char*)smh + kst + 32) = *(const uint4*)(qp + 16);
        *(uint4*)((char*)smh + kst + 48) = *(const uint4*)(qp + 24);
    }
    __syncthreads();

    // ---- preload Q fragments (4 k16 steps over d=64) ----
    uint32_t qf[4][4];
    #pragma unroll
    for (int s = 0; s < 4; s++) {
        uint32_t addr = qsb + (uint32_t)((wq + (lane & 15)) * ATS * 2
                       + (s * 2 + (lane >> 4)) * 16);
        ldsm_x4(qf[s][0], qf[s][1], qf[s][2], qf[s][3], addr);
    }

    const __half* Kp0 = K + ((size_t)(b * S_ + row)) * D_ + h * HD_ + part * 32;
    const __half* Vp0 = V + ((size_t)(b * S_ + row)) * D_ + h * HD_ + part * 32;

    float C[8][4];
    float mr[2] = {-1e30f, -1e30f};
    float lr[2] = {0.f, 0.f};

    float* arow0 = attn + ((size_t)bh * S_ + qt * 128 + wq + g) * S_;
    float* arow1 = arow0 + (size_t)8 * S_;

    // ================= pass 1: QK^T -> raw scores + stats =================
    {
        const __half* kp = Kp0;
        CP16(stg + kst,      kp);       CP16(stg + kst + 16, kp + 8);
        CP16(stg + kst + 32, kp + 16);  CP16(stg + kst + 48, kp + 24);
        CP_COMMIT();
    }
    for (int kt = 0; kt < 8; kt++) {
        if (kt + 1 < 8) {
            uint32_t so = stg + (uint32_t)(((kt + 1) & 1) * AT_TILE * 2);
            const __half* kp = Kp0 + (size_t)((kt + 1) * 128) * D_;
            CP16(so + kst,      kp);       CP16(so + kst + 16, kp + 8);
            CP16(so + kst + 32, kp + 16);  CP16(so + kst + 48, kp + 24);
            CP_COMMIT();
            CP_WAIT1();
        } else {
            CP_WAIT0();
        }
        __syncthreads();

        uint32_t kb = stg + (uint32_t)((kt & 1) * AT_TILE * 2);
        #pragma unroll
        for (int hf = 0; hf < 2; hf++) {
            #pragma unroll
            for (int j = 0; j < 8; j++)
                #pragma unroll
                for (int e = 0; e < 4; e++) C[j][e] = 0.f;

            #pragma unroll
            for (int s = 0; s < 4; s++) {
                #pragma unroll
                for (int p = 0; p < 4; p++) {
                    uint32_t b0[2], b1[2];
                    uint32_t addr = kb + (uint32_t)((hf * 64 + p * 16 + (lane & 7) + ((lane & 16) >> 1)) * ATS * 2
                                   + (s * 2 + ((lane >> 3) & 1)) * 16);
                    ldsm_x4(b0[0], b0[1], b1[0], b1[1], addr);
                    mma_f16(C[2 * p],     qf[s], b0);
                    mma_f16(C[2 * p + 1], qf[s], b1);
                }
            }

            // scale, store raw scores, update stats (per 64-col half)
            float tm0 = -1e30f, tm1 = -1e30f;
            #pragma unroll
            for (int j = 0; j < 8; j++) {
                C[j][0] *= 0.125f; C[j][1] *= 0.125f;
                C[j][2] *= 0.125f; C[j][3] *= 0.125f;
                int cc = kt * 128 + hf * 64 + j * 8 + 2 * t;
                *(float2*)(arow0 + cc) = make_float2(C[j][0], C[j][1]);
                *(float2*)(arow1 + cc) = make_float2(C[j][2], C[j][3]);
                tm0 = fmaxf(tm0, fmaxf(C[j][0], C[j][1]));
                tm1 = fmaxf(tm1, fmaxf(C[j][2], C[j][3]));
            }
            #pragma unroll
            for (int o = 1; o <= 2; o <<= 1) {
                tm0 = fmaxf(tm0, __shfl_xor_sync(0xffffffffu, tm0, o));
                tm1 = fmaxf(tm1, __shfl_xor_sync(0xffffffffu, tm1, o));
            }
            float n0 = fmaxf(mr[0], tm0), n1 = fmaxf(mr[1], tm1);
            lr[0] *= fast_exp(mr[0] - n0);
            lr[1] *= fast_exp(mr[1] - n1);
            mr[0] = n0; mr[1] = n1;
            #pragma unroll
            for (int j = 0; j < 8; j++) {
                lr[0] += fast_exp(C[j][0] - n0) + fast_exp(C[j][1] - n0);
                lr[1] += fast_exp(C[j][2] - n1) + fast_exp(C[j][3] - n1);
            }
        }
        __syncthreads();
    }
    #pragma unroll
    for (int o = 1; o <= 2; o <<= 1) {
        lr[0] += __shfl_xor_sync(0xffffffffu, lr[0], o);
        lr[1] += __shfl_xor_sync(0xffffffffu, lr[1], o);
    }
    const float il0 = 1.f / lr[0];
    const float il1 = 1.f / lr[1];

    // ================= pass 2: read scores, normalize, PV =================
    float pv[8][4];
    #pragma unroll
    for (int n = 0; n < 8; n++)
        #pragma unroll
        for (int e = 0; e < 4; e++) pv[n][e] = 0.f;

    {
        const __half* vp = Vp0;
        CP16(stg + kst,      vp);       CP16(stg + kst + 16, vp + 8);
        CP16(stg + kst + 32, vp + 16);  CP16(stg + kst + 48, vp + 24);
        CP_COMMIT();
    }
    for (int kt = 0; kt < 8; kt++) {
        if (kt + 1 < 8) {
            uint32_t so = stg + (uint32_t)(((kt + 1) & 1) * AT_TILE * 2);
            const __half* vp = Vp0 + (size_t)((kt + 1) * 128) * D_;
            CP16(so + kst,      vp);       CP16(so + kst + 16, vp + 8);
            CP16(so + kst + 32, vp + 16);  CP16(so + kst + 48, vp + 24);
            CP_COMMIT();
            CP_WAIT1();
        } else {
            CP_WAIT0();
        }
        __syncthreads();

        uint32_t vb = stg + (uint32_t)((kt & 1) * AT_TILE * 2);
        #pragma unroll
        for (int hf = 0; hf < 2; hf++) {
            // read raw scores back (L2-hot), normalize, write final attn
            #pragma unroll
            for (int j = 0; j < 8; j++) {
                int cc = kt * 128 + hf * 64 + j * 8 + 2 * t;
                float2 a0 = *(const float2*)(arow0 + cc);
                float2 a1 = *(const float2*)(arow1 + cc);
                C[j][0] = fast_exp(a0.x - mr[0]) * il0;
                C[j][1] = fast_exp(a0.y - mr[0]) * il0;
                C[j][2] = fast_exp(a1.x - mr[1]) * il1;
                C[j][3] = fast_exp(a1.y - mr[1]) * il1;
                *(float2*)(arow0 + cc) = make_float2(C[j][0], C[j][1]);
                *(float2*)(arow1 + cc) = make_float2(C[j][2], C[j][3]);
            }

            // PV: P fragments from registers, V via trans ldmatrix
            #pragma unroll
            for (int s2 = 0; s2 < 4; s2++) {
                uint32_t pa[4];
                pa[0] = f2h2(C[2 * s2][0],     C[2 * s2][1]);
                pa[1] = f2h2(C[2 * s2][2],     C[2 * s2][3]);
                pa[2] = f2h2(C[2 * s2 + 1][0], C[2 * s2 + 1][1]);
                pa[3] = f2h2(C[2 * s2 + 1][2], C[2 * s2 + 1][3]);
                #pragma unroll
                for (int p = 0; p < 4; p++) {
                    uint32_t b0[2], b1[2];
                    uint32_t addr = vb + (uint32_t)(((hf * 4 + s2) * 16 + (lane & 15)) * ATS * 2
                                   + (p * 2 + (lane >> 4)) * 16);
                    ldsm_x4_t(b0[0], b0[1], b1[0], b1[1], addr);
                    mma_f16(pv[2 * p],     pa, b0);
                    mma_f16(pv[2 * p + 1], pa, b1);
                }
            }
        }
        __syncthreads();
    }

    // ---- write ctx (fp16) ----
    __half* crow0 = ctx + ((size_t)(b * S_ + qt * 128 + wq + g)) * D_ + h * HD_;
    __half* crow1 = crow0 + (size_t)8 * D_;
    #pragma unroll
    for (int n = 0; n < 8; n++) {
        *(uint32_t*)(crow0 + n * 8 + 2 * t) = f2h2(pv[n][0], pv[n][1]);
        *(uint32_t*)(crow1 + n * 8 + 2 * t) = f2h2(pv[n][2], pv[n][3]);
    }
}

// ---------------------------------------------------------------------------
extern "C" void kernel_launch(void* const* d_in, const int* in_sizes, int n_in,
                              void* d_out, int out_size) {
    const float* x  = (const float*)d_in[0];
    const float* Wq = (const float*)d_in[1];
    const float* bq = (const float*)d_in[2];
    const float* Wk = (const float*)d_in[3];
    const float* bk = (const float*)d_in[4];
    const float* Wv = (const float*)d_in[5];
    const float* bv = (const float*)d_in[6];
    const float* Wo = (const float*)d_in[7];
    const float* bo = (const float*)d_in[8];

    float* out = (float*)d_out;
    const size_t OUT_ELEMS = (size_t)B_ * S_ * D_;
    float* attn_ptr = out + OUT_ELEMS;   // (out, attn) concatenated

    __half* xh; cudaGetSymbolAddress((void**)&xh, g_xh);
    __half* Wh; cudaGetSymbolAddress((void**)&Wh, g_Wh);
    __half* Qh; cudaGetSymbolAddress((void**)&Qh, g_Qh);
    __half* Kh; cudaGetSymbolAddress((void**)&Kh, g_Kh);
    __half* Vh; cudaGetSymbolAddress((void**)&Vh, g_Vh);
    __half* Ch; cudaGetSymbolAddress((void**)&Ch, g_Ch);
    __half* Wh0 = Wh;
    __half* Wh1 = Wh + (size_t)D_ * D_;
    __half* Wh2 = Wh + 2 * (size_t)D_ * D_;
    __half* Wh3 = Wh + 3 * (size_t)D_ * D_;

    cudaFuncSetAttribute(attn_fused, cudaFuncAttributeMaxDynamicSharedMemorySize,
                         ATT_SMEM);

    // convert inputs to fp16
    const int NX = MROWS * D_;       // 8388608
    const int NW = D_ * D_;          // 1048576
    f32_to_f16<<<NX / 8 / 256, 256>>>(x,  xh,  NX);
    f32_to_f16<<<NW / 8 / 256, 256>>>(Wq, Wh0, NW);
    f32_to_f16<<<NW / 8 / 256, 256>>>(Wk, Wh1, NW);
    f32_to_f16<<<NW / 8 / 256, 256>>>(Wv, Wh2, NW);
    f32_to_f16<<<NW / 8 / 256, 256>>>(Wo, Wh3, NW);

    // projections (fp16 in/out, 2 CTAs/SM)
    dim3 gProj(D_ / 128, MROWS / 128);          // (8, 64)
    proj_h<true><<<gProj, 256>>>(xh, Wh0, bq, Qh);
    proj_h<true><<<gProj, 256>>>(xh, Wh1, bk, Kh);
    proj_h<true><<<gProj, 256>>>(xh, Wh2, bv, Vh);

    // fused scores + softmax + attn write + AV (score-stash, 2 CTAs/SM)
    dim3 gAttn(S_ / 128, B_ * H_);              // (8, 128)
    attn_fused<<<gAttn, 256, ATT_SMEM>>>(Qh, Kh, Vh, attn_ptr, Ch);

    // output projection (fp16 in, fp32 out)
    proj_h<false><<<gProj, 256>>>(Ch, Wh3, bo, out);

    (void)n_in; (void)in_sizes; (void)out_size;
}